// round 12
// baseline (speedup 1.0000x reference)
#include <cuda_runtime.h>
#include <cuda_fp16.h>
#include <cstdint>

// ---------------- problem constants ----------------
#define BATCH    8192
#define IN_DIM   512
#define NUM_TREE 64
#define NI       31
#define NL       32
#define ODIM     16

// ---------------- GEMM tiling (fp16 m16n8k16, fragment-major, direct LDG) ----------------
#define BM       128
#define BN       256         // 8 trees * 32 padded cols
#define NK16     (IN_DIM / 16)   // 32 k16 steps
#define THREADS  256         // 8 warps: 2 m-groups x 4 n-groups, 64x64 warp tiles
#define NGRP     8           // N groups (8 * 256 = 2048 padded nodes)

// smem: epilogue union only (no GEMM staging at all)
#define P_PITCH   261
#define UOFF_P    0u                           // float[128*261] = 133632 B
#define UOFF_LF   133632u                      // float[8*32*16] = 16384 B
#define UOFF_BIAS 150016u                      // float[256]     = 1024 B
#define SMEM_TOTAL 151040u

// ---------------- device scratch ----------------
// A fragments (fp16x2 words): [512 mtiles][32 k16][32 lanes][4 regs] = 2.10M u32 (8.4 MB)
__device__ __align__(16) uint32_t g_A[(size_t)BATCH * IN_DIM / 2];
// B fragments (fp16x2 words): [256 ntiles][32 k16][32 lanes][2 regs] = 524k u32 (2 MB)
__device__ __align__(16) uint32_t g_B[(size_t)2048 * IN_DIM / 2];
__device__ __align__(16) float g_bp[2048];
__device__ __align__(16) float g_leafs_sm[NUM_TREE * NL * ODIM];
__device__ __align__(16) float g_outp[(size_t)16 * BATCH * ODIM];  // 16 partials, 8 MB

// ---------------- helpers ----------------
__device__ __forceinline__ void ldg128(uint32_t* r, const uint32_t* p) {
    asm volatile("ld.global.nc.v4.b32 {%0,%1,%2,%3}, [%4];"
                 : "=r"(r[0]), "=r"(r[1]), "=r"(r[2]), "=r"(r[3]) : "l"(p));
}
__device__ __forceinline__ void ldg64(uint32_t* r, const uint32_t* p) {
    asm volatile("ld.global.nc.v2.b32 {%0,%1}, [%2];" : "=r"(r[0]), "=r"(r[1]) : "l"(p));
}
__device__ __forceinline__ void mma_fp16(float& c0, float& c1, float& c2, float& c3,
                                         uint32_t a0, uint32_t a1, uint32_t a2, uint32_t a3,
                                         uint32_t b0, uint32_t b1) {
    asm volatile("mma.sync.aligned.m16n8k16.row.col.f32.f16.f16.f32 "
                 "{%0,%1,%2,%3}, {%4,%5,%6,%7}, {%8,%9}, {%0,%1,%2,%3};"
                 : "+f"(c0), "+f"(c1), "+f"(c2), "+f"(c3)
                 : "r"(a0), "r"(a1), "r"(a2), "r"(a3), "r"(b0), "r"(b1));
}

// ---------------- prep kernels ----------------
__global__ void leafs_softmax_kernel(const float* __restrict__ leafs) {
    int i = blockIdx.x * blockDim.x + threadIdx.x;
    if (i >= NUM_TREE * NL) return;
    const float* src = leafs + i * ODIM;
    float m = src[0];
#pragma unroll
    for (int o = 1; o < ODIM; o++) m = fmaxf(m, src[o]);
    float e[ODIM], sum = 0.f;
#pragma unroll
    for (int o = 0; o < ODIM; o++) { e[o] = __expf(src[o] - m); sum += e[o]; }
    float inv = 1.0f / sum;
#pragma unroll
    for (int o = 0; o < ODIM; o++) g_leafs_sm[i * ODIM + o] = e[o] * inv;
}

// x -> fp16x2 A fragments, m16n8k16 layout: [mtile][k16][lane][reg]
__global__ void prep_x_kernel(const float* __restrict__ x) {
    int i = blockIdx.x * blockDim.x + threadIdx.x;   // 0 .. BATCH*IN_DIM/2-1
    int mtile = i >> 12;
    int rem   = i & 4095;
    int step  = rem >> 7;
    int rem2  = rem & 127;
    int lane  = rem2 >> 2;
    int reg   = rem2 & 3;
    int g = lane >> 2, t = lane & 3;
    int row = mtile * 16 + g + (reg & 1) * 8;
    int k0  = step * 16 + 2 * t + ((reg >> 1) & 1) * 8;
    const float* xp = x + (size_t)row * IN_DIM + k0;
    __half2 h = __floats2half2_rn(xp[0], xp[1]);
    g_A[i] = *(const uint32_t*)&h;
}

// W (tree-permuted, node31 zero) -> fp16x2 B fragments: [ntile][k16][lane][reg]
__global__ void prep_w_kernel(const float* __restrict__ W, const float* __restrict__ b) {
    int i = blockIdx.x * blockDim.x + threadIdx.x;   // 0 .. 2048*IN_DIM/2-1
    int ntile = i >> 11;
    int rem   = i & 2047;
    int step  = rem >> 6;
    int rem2  = rem & 63;
    int lane  = rem2 >> 1;
    int reg   = rem2 & 1;
    int g = lane >> 2, t = lane & 3;
    int n = ntile * 8 + g;
    int tree = n >> 5, ii = n & 31;
    int k0 = step * 16 + 2 * t + reg * 8;
    float v0 = 0.f, v1 = 0.f;
    if (ii < 31) {
        const float* wp = W + (size_t)(tree * 31 + ii) * IN_DIM + k0;
        v0 = wp[0]; v1 = wp[1];
    }
    __half2 h = __floats2half2_rn(v0, v1);
    g_B[i] = *(const uint32_t*)&h;
    if (step == 0 && t == 0 && reg == 0)
        g_bp[n] = (ii < 31) ? b[tree * 31 + ii] : 0.f;
}

// ---------------- fused GEMM (direct-LDG fp16 mma.sync) + routing kernel ----------------
__global__ __launch_bounds__(THREADS, 1)
void dndf_mma_kernel() {
    extern __shared__ char smem[];

    const int tid = threadIdx.x;
    const int wid = tid >> 5;
    const int lid = tid & 31;
    const int wm = wid & 1;          // 2 m-groups of 64 rows (4 mtiles)
    const int wn = wid >> 1;         // 4 n-groups of 64 cols (8 ntiles)
    const int bm8  = blockIdx.y * 8;    // first mtile of CTA
    const int bn32 = blockIdx.x * 32;   // first ntile of CTA
    const int mrow_base = blockIdx.y * BM;
    const int ncol_base = blockIdx.x * BN;

    float* p_s    = (float*)(smem + UOFF_P);
    float* lf_s   = (float*)(smem + UOFF_LF);
    float* bias_s = (float*)(smem + UOFF_BIAS);

    // ---- stage bias + leaf tables BEFORE mainloop (sync after mainloop covers it) ----
    bias_s[tid] = g_bp[ncol_base + tid];
    {
        const float4* src = (const float4*)&g_leafs_sm[(size_t)(blockIdx.x * 8) * NL * ODIM];
        float4* dst = (float4*)lf_s;
#pragma unroll
        for (int i = 0; i < 4; i++) dst[tid + i * THREADS] = src[tid + i * THREADS];
    }

    // ---- fragment pointers ----
    // A: mtile stride 4096 u32 (16KB), k16 stride 128 u32 (512B)
    // B: ntile stride 2048 u32 (8KB),  k16 stride 64 u32 (256B)
    const uint32_t* a_ptr = g_A + ((size_t)(bm8 + wm * 4) * 4096) + lid * 4;
    const uint32_t* b_ptr = g_B + ((size_t)(bn32 + wn * 8) * 2048) + lid * 2;

    float acc[4][8][4];
#pragma unroll
    for (int i = 0; i < 4; i++)
#pragma unroll
        for (int j = 0; j < 8; j++)
#pragma unroll
            for (int r = 0; r < 4; r++) acc[i][j][r] = 0.f;

    uint32_t a[2][4][4], b[2][8][2];
    // preload k16 = 0 into buffer 0
#pragma unroll
    for (int mi = 0; mi < 4; mi++) ldg128(a[0][mi], a_ptr + mi * 4096);
#pragma unroll
    for (int nb = 0; nb < 8; nb++) ldg64(b[0][nb], b_ptr + nb * 2048);

#pragma unroll 1
    for (int k = 0; k < NK16; k += 2) {
        // --- half 1: prefetch k+1 into buf1, MMA buf0 ---
        {
            const uint32_t* ap = a_ptr + (size_t)(k + 1) * 128;
            const uint32_t* bp = b_ptr + (size_t)(k + 1) * 64;
#pragma unroll
            for (int mi = 0; mi < 4; mi++) ldg128(a[1][mi], ap + mi * 4096);
#pragma unroll
            for (int nb = 0; nb < 8; nb++) ldg64(b[1][nb], bp + nb * 2048);
#pragma unroll
            for (int mi = 0; mi < 4; mi++)
#pragma unroll
                for (int nb = 0; nb < 8; nb++)
                    mma_fp16(acc[mi][nb][0], acc[mi][nb][1], acc[mi][nb][2], acc[mi][nb][3],
                             a[0][mi][0], a[0][mi][1], a[0][mi][2], a[0][mi][3],
                             b[0][nb][0], b[0][nb][1]);
        }
        // --- half 2: prefetch k+2 into buf0 (if any), MMA buf1 ---
        {
            if (k + 2 < NK16) {
                const uint32_t* ap = a_ptr + (size_t)(k + 2) * 128;
                const uint32_t* bp = b_ptr + (size_t)(k + 2) * 64;
#pragma unroll
                for (int mi = 0; mi < 4; mi++) ldg128(a[0][mi], ap + mi * 4096);
#pragma unroll
                for (int nb = 0; nb < 8; nb++) ldg64(b[0][nb], bp + nb * 2048);
            }
#pragma unroll
            for (int mi = 0; mi < 4; mi++)
#pragma unroll
                for (int nb = 0; nb < 8; nb++)
                    mma_fp16(acc[mi][nb][0], acc[mi][nb][1], acc[mi][nb][2], acc[mi][nb][3],
                             a[1][mi][0], a[1][mi][1], a[1][mi][2], a[1][mi][3],
                             b[1][nb][0], b[1][nb][1]);
        }
    }

    __syncthreads();   // staging writes visible; smem p_s free to fill

    // ---- sigmoid(acc + bias) -> p_s, tree-interleaved: p_s[row][node*8 + tree] ----
#pragma unroll
    for (int mi = 0; mi < 4; mi++) {
#pragma unroll
        for (int nb = 0; nb < 8; nb++) {
            const int colb = wn * 64 + nb * 8 + (lid & 3) * 2;
            const int rowb = wm * 64 + mi * 16 + (lid >> 2);
#pragma unroll
            for (int r = 0; r < 4; r++) {
                const int row = rowb + (r >> 1) * 8;
                const int col = colb + (r & 1);           // 0..255 = tree*32 + node
                const int icol = (col & 31) * 8 + (col >> 5);
                const float v = acc[mi][nb][r] + bias_s[col];
                p_s[row * P_PITCH + icol] = 1.0f / (1.0f + __expf(-v));
            }
        }
    }
    __syncthreads();

    // ---- routing + leaf contraction: 1024 tasks (row, tree), 4 per thread ----
    // warp wid owns rows [wid*16, wid*16+16); lane quad = 4 trees.
#pragma unroll 1
    for (int j = 0; j < 4; j++) {
        const int tq = lid & 3;
        const int t = tq + 4 * (j & 1);        // tree within CTA group (0..7)
        const int row = wid * 16 + (lid >> 2) + (j >> 1) * 8;
        const float4* ls4 = (const float4*)&lf_s[(t * NL) * ODIM];
        const float* P = &p_s[row * P_PITCH + t];   // node i at P[i*8]

        float bb[4], cc[8], dd[16];
        {
            float p0 = P[0];
            float p1 = P[8], p2 = P[16];
            float s01 = p0 * p1;
            float s02 = p2 - p0 * p2;      // (1-p0)*p2
            bb[0] = s01;         bb[1] = p0 - s01;
            bb[2] = s02;         bb[3] = (1.0f - p0) - s02;
        }
#pragma unroll
        for (int q = 0; q < 4; q++) {
            float pv = P[(3 + q) * 8];
            float s = bb[q] * pv;
            cc[2 * q] = s; cc[2 * q + 1] = bb[q] - s;
        }
#pragma unroll
        for (int q = 0; q < 8; q++) {
            float pv = P[(7 + q) * 8];
            float s = cc[q] * pv;
            dd[2 * q] = s; dd[2 * q + 1] = cc[q] - s;
        }

        float oacc[ODIM];
#pragma unroll
        for (int o = 0; o < ODIM; o++) oacc[o] = 0.f;

#pragma unroll
        for (int q = 0; q < 16; q++) {
            float pv = P[(15 + q) * 8];
            float r0 = dd[q] * pv;
            float r1 = dd[q] - r0;
            {
                float4 v0 = ls4[(2 * q) * 4 + 0], v1 = ls4[(2 * q) * 4 + 1];
                float4 v2 = ls4[(2 * q) * 4 + 2], v3 = ls4[(2 * q) * 4 + 3];
                oacc[0]  = fmaf(r0, v0.x, oacc[0]);  oacc[1]  = fmaf(r0, v0.y, oacc[1]);
                oacc[2]  = fmaf(r0, v0.z, oacc[2]);  oacc[3]  = fmaf(r0, v0.w, oacc[3]);
                oacc[4]  = fmaf(r0, v1.x, oacc[4]);  oacc[5]  = fmaf(r0, v1.y, oacc[5]);
                oacc[6]  = fmaf(r0, v1.z, oacc[6]);  oacc[7]  = fmaf(r0, v1.w, oacc[7]);
                oacc[8]  = fmaf(r0, v2.x, oacc[8]);  oacc[9]  = fmaf(r0, v2.y, oacc[9]);
                oacc[10] = fmaf(r0, v2.z, oacc[10]); oacc[11] = fmaf(r0, v2.w, oacc[11]);
                oacc[12] = fmaf(r0, v3.x, oacc[12]); oacc[13] = fmaf(r0, v3.y, oacc[13]);
                oacc[14] = fmaf(r0, v3.z, oacc[14]); oacc[15] = fmaf(r0, v3.w, oacc[15]);
            }
            {
                float4 v0 = ls4[(2 * q + 1) * 4 + 0], v1 = ls4[(2 * q + 1) * 4 + 1];
                float4 v2 = ls4[(2 * q + 1) * 4 + 2], v3 = ls4[(2 * q + 1) * 4 + 3];
                oacc[0]  = fmaf(r1, v0.x, oacc[0]);  oacc[1]  = fmaf(r1, v0.y, oacc[1]);
                oacc[2]  = fmaf(r1, v0.z, oacc[2]);  oacc[3]  = fmaf(r1, v0.w, oacc[3]);
                oacc[4]  = fmaf(r1, v1.x, oacc[4]);  oacc[5]  = fmaf(r1, v1.y, oacc[5]);
                oacc[6]  = fmaf(r1, v1.z, oacc[6]);  oacc[7]  = fmaf(r1, v1.w, oacc[7]);
                oacc[8]  = fmaf(r1, v2.x, oacc[8]);  oacc[9]  = fmaf(r1, v2.y, oacc[9]);
                oacc[10] = fmaf(r1, v2.z, oacc[10]); oacc[11] = fmaf(r1, v2.w, oacc[11]);
                oacc[12] = fmaf(r1, v3.x, oacc[12]); oacc[13] = fmaf(r1, v3.y, oacc[13]);
                oacc[14] = fmaf(r1, v3.z, oacc[14]); oacc[15] = fmaf(r1, v3.w, oacc[15]);
            }
        }

        // sum the 4 trees of this quad (lane-quad butterfly)
#pragma unroll
        for (int o = 0; o < ODIM; o++) {
            oacc[o] += __shfl_xor_sync(0xffffffffu, oacc[o], 1);
            oacc[o] += __shfl_xor_sync(0xffffffffu, oacc[o], 2);
        }
        // all 4 lanes hold the quad sum; lane tq writes float4 quarter tq
        float4 v = make_float4(oacc[tq * 4 + 0], oacc[tq * 4 + 1],
                               oacc[tq * 4 + 2], oacc[tq * 4 + 3]);
        *(float4*)&g_outp[((size_t)(blockIdx.x * 2 + (j & 1)) * BATCH + mrow_base + row) * ODIM
                          + tq * 4] = v;
    }
}

// ---------------- final reduce over the 16 partials ----------------
__global__ void reduce_kernel(float* __restrict__ out) {
    int i = blockIdx.x * blockDim.x + threadIdx.x;   // 32768 float4s
    float4 acc = make_float4(0.f, 0.f, 0.f, 0.f);
#pragma unroll
    for (int g = 0; g < 16; g++) {
        float4 v = ((const float4*)g_outp)[(size_t)g * (BATCH * 4) + i];
        acc.x += v.x; acc.y += v.y; acc.z += v.z; acc.w += v.w;
    }
    const float s = 1.0f / NUM_TREE;
    ((float4*)out)[i] = make_float4(acc.x * s, acc.y * s, acc.z * s, acc.w * s);
}

// ---------------- launch ----------------
extern "C" void kernel_launch(void* const* d_in, const int* in_sizes, int n_in,
                              void* d_out, int out_size) {
    const float* x     = (const float*)d_in[0];   // [8192, 512]
    const float* W     = (const float*)d_in[1];   // [1984, 512]
    const float* b     = (const float*)d_in[2];   // [1984]
    const float* leafs = (const float*)d_in[3];   // [64, 32, 16]
    float* out = (float*)d_out;                   // [8192, 16]

    leafs_softmax_kernel<<<(NUM_TREE * NL + 255) / 256, 256>>>(leafs);
    prep_x_kernel<<<(BATCH * IN_DIM / 2) / 256, 256>>>(x);
    prep_w_kernel<<<(2048 * IN_DIM / 2) / 256, 256>>>(W, b);

    cudaFuncSetAttribute(dndf_mma_kernel,
                         cudaFuncAttributeMaxDynamicSharedMemorySize, SMEM_TOTAL);
    dndf_mma_kernel<<<dim3(NGRP, BATCH / BM), THREADS, SMEM_TOTAL>>>();

    reduce_kernel<<<(BATCH * 4) / 256, 256>>>(out);
}

// round 13
// speedup vs baseline: 1.0949x; 1.0949x over previous
#include <cuda_runtime.h>
#include <cuda_bf16.h>
#include <cstdint>

// ---------------- problem constants ----------------
#define BATCH    8192
#define IN_DIM   512
#define NUM_TREE 64
#define NI       31
#define NL       32
#define ODIM     16

// ---------------- GEMM tiling (bf16 m16n8k16, fragment-major, direct LDG) ----------------
#define BM       128
#define BN       256         // 8 trees * 32 padded cols
#define NK16     (IN_DIM / 16)   // 32 k16 steps
#define THREADS  512         // 16 warps: 2 m-groups x 8 n-groups, 64x32 warp tiles
#define NGRP     8           // N groups (8 * 256 = 2048 padded nodes)

// smem: epilogue union only (no GEMM staging at all)
#define P_PITCH   261
#define UOFF_P    0u                           // float[128*261] = 133632 B
#define UOFF_LF   133632u                      // float[8*32*16] = 16384 B
#define UOFF_BIAS 150016u                      // float[256]     = 1024 B
#define SMEM_TOTAL 151040u

// ---------------- device scratch ----------------
// A fragments (bf16x2 words): [512 mtiles][32 k16][32 lanes][4 regs] = 2.10M u32 (8.4 MB)
__device__ __align__(16) uint32_t g_A[(size_t)BATCH * IN_DIM / 2];
// B fragments (bf16x2 words): [256 ntiles][32 k16][32 lanes][2 regs] = 524k u32 (2 MB)
__device__ __align__(16) uint32_t g_B[(size_t)2048 * IN_DIM / 2];
__device__ __align__(16) float g_bp[2048];
__device__ __align__(16) float g_leafs_sm[NUM_TREE * NL * ODIM];
__device__ __align__(16) float g_outp[(size_t)16 * BATCH * ODIM];  // 16 partials, 8 MB

// ---------------- helpers ----------------
__device__ __forceinline__ void ldg128(uint32_t* r, const uint32_t* p) {
    asm volatile("ld.global.nc.v4.b32 {%0,%1,%2,%3}, [%4];"
                 : "=r"(r[0]), "=r"(r[1]), "=r"(r[2]), "=r"(r[3]) : "l"(p));
}
__device__ __forceinline__ void ldg64(uint32_t* r, const uint32_t* p) {
    asm volatile("ld.global.nc.v2.b32 {%0,%1}, [%2];" : "=r"(r[0]), "=r"(r[1]) : "l"(p));
}
__device__ __forceinline__ void mma_bf16(float& c0, float& c1, float& c2, float& c3,
                                         uint32_t a0, uint32_t a1, uint32_t a2, uint32_t a3,
                                         uint32_t b0, uint32_t b1) {
    asm volatile("mma.sync.aligned.m16n8k16.row.col.f32.bf16.bf16.f32 "
                 "{%0,%1,%2,%3}, {%4,%5,%6,%7}, {%8,%9}, {%0,%1,%2,%3};"
                 : "+f"(c0), "+f"(c1), "+f"(c2), "+f"(c3)
                 : "r"(a0), "r"(a1), "r"(a2), "r"(a3), "r"(b0), "r"(b1));
}
__device__ __forceinline__ uint32_t pack_bf16x2(float lo, float hi) {
    __nv_bfloat162 h;
    h.x = __float2bfloat16(lo);
    h.y = __float2bfloat16(hi);
    return *(const uint32_t*)&h;
}

// ---------------- prep kernels ----------------
__global__ void leafs_softmax_kernel(const float* __restrict__ leafs) {
    int i = blockIdx.x * blockDim.x + threadIdx.x;
    if (i >= NUM_TREE * NL) return;
    const float* src = leafs + i * ODIM;
    float m = src[0];
#pragma unroll
    for (int o = 1; o < ODIM; o++) m = fmaxf(m, src[o]);
    float e[ODIM], sum = 0.f;
#pragma unroll
    for (int o = 0; o < ODIM; o++) { e[o] = __expf(src[o] - m); sum += e[o]; }
    float inv = 1.0f / sum;
#pragma unroll
    for (int o = 0; o < ODIM; o++) g_leafs_sm[i * ODIM + o] = e[o] * inv;
}

// x -> bf16x2 A fragments, m16n8k16 layout: [mtile][k16][lane][reg]
// reg0: (row g,   k0..k0+1)  reg1: (row g+8, k0..k0+1)
// reg2: (row g,   k0+8..+9)  reg3: (row g+8, k0+8..+9),  k0 = 16*step + 2t
__global__ void prep_x_kernel(const float* __restrict__ x) {
    int i = blockIdx.x * blockDim.x + threadIdx.x;   // 0 .. BATCH*IN_DIM/2-1
    int mtile = i >> 12;
    int rem   = i & 4095;
    int step  = rem >> 7;
    int rem2  = rem & 127;
    int lane  = rem2 >> 2;
    int reg   = rem2 & 3;
    int g = lane >> 2, t = lane & 3;
    int row = mtile * 16 + g + (reg & 1) * 8;
    int k0  = step * 16 + 2 * t + ((reg >> 1) & 1) * 8;
    const float* xp = x + (size_t)row * IN_DIM + k0;
    g_A[i] = pack_bf16x2(xp[0], xp[1]);
}

// W (tree-permuted, node31 zero) -> bf16x2 B fragments: [ntile][k16][lane][reg]
// reg0: (n=8*ntile+g, k0..k0+1), reg1: (same n, k0+8..+9), k0 = 16*step + 2t
__global__ void prep_w_kernel(const float* __restrict__ W, const float* __restrict__ b) {
    int i = blockIdx.x * blockDim.x + threadIdx.x;   // 0 .. 2048*IN_DIM/2-1
    int ntile = i >> 11;
    int rem   = i & 2047;
    int step  = rem >> 6;
    int rem2  = rem & 63;
    int lane  = rem2 >> 1;
    int reg   = rem2 & 1;
    int g = lane >> 2, t = lane & 3;
    int n = ntile * 8 + g;
    int tree = n >> 5, ii = n & 31;
    int k0 = step * 16 + 2 * t + reg * 8;
    float v0 = 0.f, v1 = 0.f;
    if (ii < 31) {
        const float* wp = W + (size_t)(tree * 31 + ii) * IN_DIM + k0;
        v0 = wp[0]; v1 = wp[1];
    }
    g_B[i] = pack_bf16x2(v0, v1);
    if (step == 0 && t == 0 && reg == 0)
        g_bp[n] = (ii < 31) ? b[tree * 31 + ii] : 0.f;
}

// ---------------- fused GEMM (direct-LDG bf16 mma.sync) + routing kernel ----------------
__global__ __launch_bounds__(THREADS, 1)
void dndf_mma_kernel() {
    extern __shared__ char smem[];

    const int tid = threadIdx.x;
    const int wid = tid >> 5;
    const int lid = tid & 31;
    const int wm = wid & 1;          // 2 m-groups of 64 rows (4 mtiles)
    const int wn = wid >> 1;         // 8 n-groups of 32 cols (4 ntiles)
    const int bm8  = blockIdx.y * 8;    // first mtile of CTA
    const int bn32 = blockIdx.x * 32;   // first ntile of CTA
    const int mrow_base = blockIdx.y * BM;
    const int ncol_base = blockIdx.x * BN;

    float* p_s    = (float*)(smem + UOFF_P);
    float* lf_s   = (float*)(smem + UOFF_LF);
    float* bias_s = (float*)(smem + UOFF_BIAS);

    // ---- stage bias + leaf tables BEFORE mainloop (sync after mainloop covers it) ----
    if (tid < 256) bias_s[tid] = g_bp[ncol_base + tid];
    {
        const float4* src = (const float4*)&g_leafs_sm[(size_t)(blockIdx.x * 8) * NL * ODIM];
        float4* dst = (float4*)lf_s;
        dst[tid] = src[tid];                   // 1024 float4s, 512 threads x2
        dst[tid + 512] = src[tid + 512];
    }

    // ---- fragment pointers: contiguous per (tile, k16, lane) ----
    // A: mtile stride 4096 u32 (16KB), k16 stride 128 u32 (512B)
    // B: ntile stride 2048 u32 (8KB),  k16 stride 64 u32 (256B)
    const uint32_t* a_ptr = g_A + ((size_t)(bm8 + wm * 4) * 4096) + lid * 4;
    const uint32_t* b_ptr = g_B + ((size_t)(bn32 + wn * 4) * 2048) + lid * 2;

    float acc[4][4][4];
#pragma unroll
    for (int i = 0; i < 4; i++)
#pragma unroll
        for (int j = 0; j < 4; j++)
#pragma unroll
            for (int r = 0; r < 4; r++) acc[i][j][r] = 0.f;

    uint32_t a[2][4][4], b[2][4][2];
    // preload k16 = 0 into buffer 0
#pragma unroll
    for (int mi = 0; mi < 4; mi++) ldg128(a[0][mi], a_ptr + mi * 4096);
#pragma unroll
    for (int nb = 0; nb < 4; nb++) ldg64(b[0][nb], b_ptr + nb * 2048);

#pragma unroll 1
    for (int k = 0; k < NK16; k += 2) {
        // --- half 1: prefetch k+1 into buf1, MMA buf0 ---
        {
            const uint32_t* ap = a_ptr + (size_t)(k + 1) * 128;
            const uint32_t* bp = b_ptr + (size_t)(k + 1) * 64;
#pragma unroll
            for (int mi = 0; mi < 4; mi++) ldg128(a[1][mi], ap + mi * 4096);
#pragma unroll
            for (int nb = 0; nb < 4; nb++) ldg64(b[1][nb], bp + nb * 2048);
#pragma unroll
            for (int mi = 0; mi < 4; mi++)
#pragma unroll
                for (int nb = 0; nb < 4; nb++)
                    mma_bf16(acc[mi][nb][0], acc[mi][nb][1], acc[mi][nb][2], acc[mi][nb][3],
                             a[0][mi][0], a[0][mi][1], a[0][mi][2], a[0][mi][3],
                             b[0][nb][0], b[0][nb][1]);
        }
        // --- half 2: prefetch k+2 into buf0 (if any), MMA buf1 ---
        {
            if (k + 2 < NK16) {
                const uint32_t* ap = a_ptr + (size_t)(k + 2) * 128;
                const uint32_t* bp = b_ptr + (size_t)(k + 2) * 64;
#pragma unroll
                for (int mi = 0; mi < 4; mi++) ldg128(a[0][mi], ap + mi * 4096);
#pragma unroll
                for (int nb = 0; nb < 4; nb++) ldg64(b[0][nb], bp + nb * 2048);
            }
#pragma unroll
            for (int mi = 0; mi < 4; mi++)
#pragma unroll
                for (int nb = 0; nb < 4; nb++)
                    mma_bf16(acc[mi][nb][0], acc[mi][nb][1], acc[mi][nb][2], acc[mi][nb][3],
                             a[1][mi][0], a[1][mi][1], a[1][mi][2], a[1][mi][3],
                             b[1][nb][0], b[1][nb][1]);
        }
    }

    __syncthreads();   // staging writes visible; smem p_s free to fill

    // ---- sigmoid(acc + bias) -> p_s, tree-interleaved: p_s[row][node*8 + tree] ----
#pragma unroll
    for (int mi = 0; mi < 4; mi++) {
#pragma unroll
        for (int nb = 0; nb < 4; nb++) {
            const int colb = wn * 32 + nb * 8 + (lid & 3) * 2;
            const int rowb = wm * 64 + mi * 16 + (lid >> 2);
#pragma unroll
            for (int r = 0; r < 4; r++) {
                const int row = rowb + (r >> 1) * 8;
                const int col = colb + (r & 1);           // 0..255 = tree*32 + node
                const int icol = (col & 31) * 8 + (col >> 5);
                const float v = acc[mi][nb][r] + bias_s[col];
                p_s[row * P_PITCH + icol] = 1.0f / (1.0f + __expf(-v));
            }
        }
    }
    __syncthreads();

    // ---- routing + leaf contraction: 1024 tasks (row, tree), 2 per thread ----
#pragma unroll 1
    for (int j = 0; j < 2; j++) {
        const int tq = lid & 3;
        const int t = tq + 4 * j;              // tree within CTA group (0..7)
        const int row = wid * 8 + (lid >> 2);
        const float4* ls4 = (const float4*)&lf_s[(t * NL) * ODIM];
        const float* P = &p_s[row * P_PITCH + t];   // node i at P[i*8]

        float bb[4], cc[8], dd[16];
        {
            float p0 = P[0];
            float p1 = P[8], p2 = P[16];
            float s01 = p0 * p1;
            float s02 = p2 - p0 * p2;      // (1-p0)*p2
            bb[0] = s01;         bb[1] = p0 - s01;
            bb[2] = s02;         bb[3] = (1.0f - p0) - s02;
        }
#pragma unroll
        for (int q = 0; q < 4; q++) {
            float pv = P[(3 + q) * 8];
            float s = bb[q] * pv;
            cc[2 * q] = s; cc[2 * q + 1] = bb[q] - s;
        }
#pragma unroll
        for (int q = 0; q < 8; q++) {
            float pv = P[(7 + q) * 8];
            float s = cc[q] * pv;
            dd[2 * q] = s; dd[2 * q + 1] = cc[q] - s;
        }

        float oacc[ODIM];
#pragma unroll
        for (int o = 0; o < ODIM; o++) oacc[o] = 0.f;

#pragma unroll
        for (int q = 0; q < 16; q++) {
            float pv = P[(15 + q) * 8];
            float r0 = dd[q] * pv;
            float r1 = dd[q] - r0;
            {
                float4 v0 = ls4[(2 * q) * 4 + 0], v1 = ls4[(2 * q) * 4 + 1];
                float4 v2 = ls4[(2 * q) * 4 + 2], v3 = ls4[(2 * q) * 4 + 3];
                oacc[0]  = fmaf(r0, v0.x, oacc[0]);  oacc[1]  = fmaf(r0, v0.y, oacc[1]);
                oacc[2]  = fmaf(r0, v0.z, oacc[2]);  oacc[3]  = fmaf(r0, v0.w, oacc[3]);
                oacc[4]  = fmaf(r0, v1.x, oacc[4]);  oacc[5]  = fmaf(r0, v1.y, oacc[5]);
                oacc[6]  = fmaf(r0, v1.z, oacc[6]);  oacc[7]  = fmaf(r0, v1.w, oacc[7]);
                oacc[8]  = fmaf(r0, v2.x, oacc[8]);  oacc[9]  = fmaf(r0, v2.y, oacc[9]);
                oacc[10] = fmaf(r0, v2.z, oacc[10]); oacc[11] = fmaf(r0, v2.w, oacc[11]);
                oacc[12] = fmaf(r0, v3.x, oacc[12]); oacc[13] = fmaf(r0, v3.y, oacc[13]);
                oacc[14] = fmaf(r0, v3.z, oacc[14]); oacc[15] = fmaf(r0, v3.w, oacc[15]);
            }
            {
                float4 v0 = ls4[(2 * q + 1) * 4 + 0], v1 = ls4[(2 * q + 1) * 4 + 1];
                float4 v2 = ls4[(2 * q + 1) * 4 + 2], v3 = ls4[(2 * q + 1) * 4 + 3];
                oacc[0]  = fmaf(r1, v0.x, oacc[0]);  oacc[1]  = fmaf(r1, v0.y, oacc[1]);
                oacc[2]  = fmaf(r1, v0.z, oacc[2]);  oacc[3]  = fmaf(r1, v0.w, oacc[3]);
                oacc[4]  = fmaf(r1, v1.x, oacc[4]);  oacc[5]  = fmaf(r1, v1.y, oacc[5]);
                oacc[6]  = fmaf(r1, v1.z, oacc[6]);  oacc[7]  = fmaf(r1, v1.w, oacc[7]);
                oacc[8]  = fmaf(r1, v2.x, oacc[8]);  oacc[9]  = fmaf(r1, v2.y, oacc[9]);
                oacc[10] = fmaf(r1, v2.z, oacc[10]); oacc[11] = fmaf(r1, v2.w, oacc[11]);
                oacc[12] = fmaf(r1, v3.x, oacc[12]); oacc[13] = fmaf(r1, v3.y, oacc[13]);
                oacc[14] = fmaf(r1, v3.z, oacc[14]); oacc[15] = fmaf(r1, v3.w, oacc[15]);
            }
        }

        // sum the 4 trees of this quad (lane-quad butterfly)
#pragma unroll
        for (int o = 0; o < ODIM; o++) {
            oacc[o] += __shfl_xor_sync(0xffffffffu, oacc[o], 1);
            oacc[o] += __shfl_xor_sync(0xffffffffu, oacc[o], 2);
        }
        // all 4 lanes hold the quad sum; lane tq writes float4 quarter tq
        float4 v = make_float4(oacc[tq * 4 + 0], oacc[tq * 4 + 1],
                               oacc[tq * 4 + 2], oacc[tq * 4 + 3]);
        *(float4*)&g_outp[((size_t)(blockIdx.x * 2 + j) * BATCH + mrow_base + row) * ODIM
                          + tq * 4] = v;
    }
}

// ---------------- final reduce over the 16 partials ----------------
__global__ void reduce_kernel(float* __restrict__ out) {
    int i = blockIdx.x * blockDim.x + threadIdx.x;   // 32768 float4s
    float4 acc = make_float4(0.f, 0.f, 0.f, 0.f);
#pragma unroll
    for (int g = 0; g < 16; g++) {
        float4 v = ((const float4*)g_outp)[(size_t)g * (BATCH * 4) + i];
        acc.x += v.x; acc.y += v.y; acc.z += v.z; acc.w += v.w;
    }
    const float s = 1.0f / NUM_TREE;
    ((float4*)out)[i] = make_float4(acc.x * s, acc.y * s, acc.z * s, acc.w * s);
}

// ---------------- launch ----------------
extern "C" void kernel_launch(void* const* d_in, const int* in_sizes, int n_in,
                              void* d_out, int out_size) {
    const float* x     = (const float*)d_in[0];   // [8192, 512]
    const float* W     = (const float*)d_in[1];   // [1984, 512]
    const float* b     = (const float*)d_in[2];   // [1984]
    const float* leafs = (const float*)d_in[3];   // [64, 32, 16]
    float* out = (float*)d_out;                   // [8192, 16]

    leafs_softmax_kernel<<<(NUM_TREE * NL + 255) / 256, 256>>>(leafs);
    prep_x_kernel<<<(BATCH * IN_DIM / 2) / 256, 256>>>(x);
    prep_w_kernel<<<(2048 * IN_DIM / 2) / 256, 256>>>(W, b);

    cudaFuncSetAttribute(dndf_mma_kernel,
                         cudaFuncAttributeMaxDynamicSharedMemorySize, SMEM_TOTAL);
    dndf_mma_kernel<<<dim3(NGRP, BATCH / BM), THREADS, SMEM_TOTAL>>>();

    reduce_kernel<<<(BATCH * 4) / 256, 256>>>(out);
}

// round 14
// speedup vs baseline: 1.1381x; 1.0395x over previous
#include <cuda_runtime.h>
#include <cuda_bf16.h>
#include <cstdint>

// ---------------- problem constants ----------------
#define BATCH    8192
#define IN_DIM   512
#define NUM_TREE 64
#define NI       31
#define NL       32
#define ODIM     16

// ---------------- GEMM tiling (bf16 m16n8k16, fragment-major, direct LDG) ----------------
#define BM       64          // 4 mtiles
#define BN       128         // 4 trees * 32 padded cols (16 ntiles)
#define NK16     (IN_DIM / 16)   // 32 k16 steps
#define THREADS  256         // 8 warps: 2 m-groups x 4 n-groups, 32x32 warp tiles
#define NGRP     16          // N groups (16 * 128 = 2048 padded nodes)

// smem: epilogue union only
#define P_PITCH   133
#define UOFF_P    0u                           // float[64*133]  = 34048 B
#define UOFF_LF   34048u                       // float[4*32*16] = 8192 B
#define UOFF_BIAS 42240u                       // float[128]     = 512 B
#define SMEM_TOTAL 42752u                      // x2 CTAs = 85.5 KB/SM

// ---------------- device scratch ----------------
// A fragments (bf16x2 words): [512 mtiles][32 k16][32 lanes][4 regs] = 8.4 MB
__device__ __align__(16) uint32_t g_A[(size_t)BATCH * IN_DIM / 2];
// B fragments (bf16x2 words): [256 ntiles][32 k16][32 lanes][2 regs] = 2 MB
__device__ __align__(16) uint32_t g_B[(size_t)2048 * IN_DIM / 2];
__device__ __align__(16) float g_bp[2048];
__device__ __align__(16) float g_leafs_sm[NUM_TREE * NL * ODIM];
__device__ __align__(16) float g_outp[(size_t)16 * BATCH * ODIM];  // 16 partials, 8 MB

// ---------------- helpers ----------------
__device__ __forceinline__ void ldg128(uint32_t* r, const uint32_t* p) {
    asm volatile("ld.global.nc.v4.b32 {%0,%1,%2,%3}, [%4];"
                 : "=r"(r[0]), "=r"(r[1]), "=r"(r[2]), "=r"(r[3]) : "l"(p));
}
__device__ __forceinline__ void ldg64(uint32_t* r, const uint32_t* p) {
    asm volatile("ld.global.nc.v2.b32 {%0,%1}, [%2];" : "=r"(r[0]), "=r"(r[1]) : "l"(p));
}
__device__ __forceinline__ void mma_bf16(float& c0, float& c1, float& c2, float& c3,
                                         uint32_t a0, uint32_t a1, uint32_t a2, uint32_t a3,
                                         uint32_t b0, uint32_t b1) {
    asm volatile("mma.sync.aligned.m16n8k16.row.col.f32.bf16.bf16.f32 "
                 "{%0,%1,%2,%3}, {%4,%5,%6,%7}, {%8,%9}, {%0,%1,%2,%3};"
                 : "+f"(c0), "+f"(c1), "+f"(c2), "+f"(c3)
                 : "r"(a0), "r"(a1), "r"(a2), "r"(a3), "r"(b0), "r"(b1));
}
__device__ __forceinline__ uint32_t pack_bf16x2(float lo, float hi) {
    __nv_bfloat162 h;
    h.x = __float2bfloat16(lo);
    h.y = __float2bfloat16(hi);
    return *(const uint32_t*)&h;
}

// ---------------- prep kernels ----------------
__global__ void leafs_softmax_kernel(const float* __restrict__ leafs) {
    int i = blockIdx.x * blockDim.x + threadIdx.x;
    if (i >= NUM_TREE * NL) return;
    const float* src = leafs + i * ODIM;
    float m = src[0];
#pragma unroll
    for (int o = 1; o < ODIM; o++) m = fmaxf(m, src[o]);
    float e[ODIM], sum = 0.f;
#pragma unroll
    for (int o = 0; o < ODIM; o++) { e[o] = __expf(src[o] - m); sum += e[o]; }
    float inv = 1.0f / sum;
#pragma unroll
    for (int o = 0; o < ODIM; o++) g_leafs_sm[i * ODIM + o] = e[o] * inv;
}

// x -> bf16x2 A fragments, m16n8k16 layout: [mtile][k16][lane][reg]
__global__ void prep_x_kernel(const float* __restrict__ x) {
    int i = blockIdx.x * blockDim.x + threadIdx.x;   // 0 .. BATCH*IN_DIM/2-1
    int mtile = i >> 12;
    int rem   = i & 4095;
    int step  = rem >> 7;
    int rem2  = rem & 127;
    int lane  = rem2 >> 2;
    int reg   = rem2 & 3;
    int g = lane >> 2, t = lane & 3;
    int row = mtile * 16 + g + (reg & 1) * 8;
    int k0  = step * 16 + 2 * t + ((reg >> 1) & 1) * 8;
    const float* xp = x + (size_t)row * IN_DIM + k0;
    g_A[i] = pack_bf16x2(xp[0], xp[1]);
}

// W (tree-permuted, node31 zero) -> bf16x2 B fragments: [ntile][k16][lane][reg]
__global__ void prep_w_kernel(const float* __restrict__ W, const float* __restrict__ b) {
    int i = blockIdx.x * blockDim.x + threadIdx.x;   // 0 .. 2048*IN_DIM/2-1
    int ntile = i >> 11;
    int rem   = i & 2047;
    int step  = rem >> 6;
    int rem2  = rem & 63;
    int lane  = rem2 >> 1;
    int reg   = rem2 & 1;
    int g = lane >> 2, t = lane & 3;
    int n = ntile * 8 + g;
    int tree = n >> 5, ii = n & 31;
    int k0 = step * 16 + 2 * t + reg * 8;
    float v0 = 0.f, v1 = 0.f;
    if (ii < 31) {
        const float* wp = W + (size_t)(tree * 31 + ii) * IN_DIM + k0;
        v0 = wp[0]; v1 = wp[1];
    }
    g_B[i] = pack_bf16x2(v0, v1);
    if (step == 0 && t == 0 && reg == 0)
        g_bp[n] = (ii < 31) ? b[tree * 31 + ii] : 0.f;
}

// ---------------- fused GEMM (direct-LDG bf16 mma.sync) + routing, 2 CTAs/SM ----------------
__global__ __launch_bounds__(THREADS, 2)
void dndf_mma_kernel() {
    extern __shared__ char smem[];

    const int tid = threadIdx.x;
    const int wid = tid >> 5;
    const int lid = tid & 31;
    const int wm = wid & 1;          // 2 m-groups of 32 rows (2 mtiles)
    const int wn = wid >> 1;         // 4 n-groups of 32 cols (4 ntiles)
    const int bm4  = blockIdx.y * 4;    // first mtile of CTA
    const int bn16 = blockIdx.x * 16;   // first ntile of CTA
    const int mrow_base = blockIdx.y * BM;
    const int ncol_base = blockIdx.x * BN;

    float* p_s    = (float*)(smem + UOFF_P);
    float* lf_s   = (float*)(smem + UOFF_LF);
    float* bias_s = (float*)(smem + UOFF_BIAS);

    // ---- stage bias + leaf tables BEFORE mainloop (sync after mainloop covers it) ----
    if (tid < 128) bias_s[tid] = g_bp[ncol_base + tid];
    {
        const float4* src = (const float4*)&g_leafs_sm[(size_t)(blockIdx.x * 4) * NL * ODIM];
        float4* dst = (float4*)lf_s;
        dst[tid] = src[tid];                   // 512 float4s, 256 threads x2
        dst[tid + 256] = src[tid + 256];
    }

    // ---- fragment pointers ----
    // A: mtile stride 4096 u32 (16KB), k16 stride 128 u32 (512B)
    // B: ntile stride 2048 u32 (8KB),  k16 stride 64 u32 (256B)
    const uint32_t* a_ptr = g_A + ((size_t)(bm4 + wm * 2) * 4096) + lid * 4;
    const uint32_t* b_ptr = g_B + ((size_t)(bn16 + wn * 4) * 2048) + lid * 2;

    float acc[2][4][4];
#pragma unroll
    for (int i = 0; i < 2; i++)
#pragma unroll
        for (int j = 0; j < 4; j++)
#pragma unroll
            for (int r = 0; r < 4; r++) acc[i][j][r] = 0.f;

    uint32_t a[2][2][4], b[2][4][2];
    // preload k16 = 0 into buffer 0
#pragma unroll
    for (int mi = 0; mi < 2; mi++) ldg128(a[0][mi], a_ptr + mi * 4096);
#pragma unroll
    for (int nb = 0; nb < 4; nb++) ldg64(b[0][nb], b_ptr + nb * 2048);

#pragma unroll 1
    for (int k = 0; k < NK16; k += 2) {
        // --- half 1: prefetch k+1 into buf1, MMA buf0 ---
        {
            const uint32_t* ap = a_ptr + (size_t)(k + 1) * 128;
            const uint32_t* bp = b_ptr + (size_t)(k + 1) * 64;
#pragma unroll
            for (int mi = 0; mi < 2; mi++) ldg128(a[1][mi], ap + mi * 4096);
#pragma unroll
            for (int nb = 0; nb < 4; nb++) ldg64(b[1][nb], bp + nb * 2048);
#pragma unroll
            for (int mi = 0; mi < 2; mi++)
#pragma unroll
                for (int nb = 0; nb < 4; nb++)
                    mma_bf16(acc[mi][nb][0], acc[mi][nb][1], acc[mi][nb][2], acc[mi][nb][3],
                             a[0][mi][0], a[0][mi][1], a[0][mi][2], a[0][mi][3],
                             b[0][nb][0], b[0][nb][1]);
        }
        // --- half 2: prefetch k+2 into buf0 (if any), MMA buf1 ---
        {
            if (k + 2 < NK16) {
                const uint32_t* ap = a_ptr + (size_t)(k + 2) * 128;
                const uint32_t* bp = b_ptr + (size_t)(k + 2) * 64;
#pragma unroll
                for (int mi = 0; mi < 2; mi++) ldg128(a[0][mi], ap + mi * 4096);
#pragma unroll
                for (int nb = 0; nb < 4; nb++) ldg64(b[0][nb], bp + nb * 2048);
            }
#pragma unroll
            for (int mi = 0; mi < 2; mi++)
#pragma unroll
                for (int nb = 0; nb < 4; nb++)
                    mma_bf16(acc[mi][nb][0], acc[mi][nb][1], acc[mi][nb][2], acc[mi][nb][3],
                             a[1][mi][0], a[1][mi][1], a[1][mi][2], a[1][mi][3],
                             b[1][nb][0], b[1][nb][1]);
        }
    }

    __syncthreads();   // staging writes visible; smem p_s free to fill

    // ---- sigmoid(acc + bias) -> p_s, tree-interleaved: p_s[row][node*4 + tree] ----
#pragma unroll
    for (int mi = 0; mi < 2; mi++) {
#pragma unroll
        for (int nb = 0; nb < 4; nb++) {
            const int colb = wn * 32 + nb * 8 + (lid & 3) * 2;
            const int rowb = wm * 32 + mi * 16 + (lid >> 2);
#pragma unroll
            for (int r = 0; r < 4; r++) {
                const int row = rowb + (r >> 1) * 8;
                const int col = colb + (r & 1);           // 0..127 = tree*32 + node
                const int icol = (col & 31) * 4 + (col >> 5);
                const float v = acc[mi][nb][r] + bias_s[col];
                p_s[row * P_PITCH + icol] = 1.0f / (1.0f + __expf(-v));
            }
        }
    }
    __syncthreads();

    // ---- routing + leaf contraction: 256 tasks (row, tree), one per thread ----
    // warp wid owns rows [wid*8, wid*8+8); lane l = (row = wid*8 + (l>>2), tree = l&3).
    {
        const int t = lid & 3;
        const int row = wid * 8 + (lid >> 2);
        const float4* ls4 = (const float4*)&lf_s[(t * NL) * ODIM];
        const float* P = &p_s[row * P_PITCH + t];   // node i at P[i*4]

        float bb[4], cc[8], dd[16];
        {
            float p0 = P[0];
            float p1 = P[4], p2 = P[8];
            float s01 = p0 * p1;
            float s02 = p2 - p0 * p2;      // (1-p0)*p2
            bb[0] = s01;         bb[1] = p0 - s01;
            bb[2] = s02;         bb[3] = (1.0f - p0) - s02;
        }
#pragma unroll
        for (int q = 0; q < 4; q++) {
            float pv = P[(3 + q) * 4];
            float s = bb[q] * pv;
            cc[2 * q] = s; cc[2 * q + 1] = bb[q] - s;
        }
#pragma unroll
        for (int q = 0; q < 8; q++) {
            float pv = P[(7 + q) * 4];
            float s = cc[q] * pv;
            dd[2 * q] = s; dd[2 * q + 1] = cc[q] - s;
        }

        float oacc[ODIM];
#pragma unroll
        for (int o = 0; o < ODIM; o++) oacc[o] = 0.f;

#pragma unroll
        for (int q = 0; q < 16; q++) {
            float pv = P[(15 + q) * 4];
            float r0 = dd[q] * pv;
            float r1 = dd[q] - r0;
            {
                float4 v0 = ls4[(2 * q) * 4 + 0], v1 = ls4[(2 * q) * 4 + 1];
                float4 v2 = ls4[(2 * q) * 4 + 2], v3 = ls4[(2 * q) * 4 + 3];
                oacc[0]  = fmaf(r0, v0.x, oacc[0]);  oacc[1]  = fmaf(r0, v0.y, oacc[1]);
                oacc[2]  = fmaf(r0, v0.z, oacc[2]);  oacc[3]  = fmaf(r0, v0.w, oacc[3]);
                oacc[4]  = fmaf(r0, v1.x, oacc[4]);  oacc[5]  = fmaf(r0, v1.y, oacc[5]);
                oacc[6]  = fmaf(r0, v1.z, oacc[6]);  oacc[7]  = fmaf(r0, v1.w, oacc[7]);
                oacc[8]  = fmaf(r0, v2.x, oacc[8]);  oacc[9]  = fmaf(r0, v2.y, oacc[9]);
                oacc[10] = fmaf(r0, v2.z, oacc[10]); oacc[11] = fmaf(r0, v2.w, oacc[11]);
                oacc[12] = fmaf(r0, v3.x, oacc[12]); oacc[13] = fmaf(r0, v3.y, oacc[13]);
                oacc[14] = fmaf(r0, v3.z, oacc[14]); oacc[15] = fmaf(r0, v3.w, oacc[15]);
            }
            {
                float4 v0 = ls4[(2 * q + 1) * 4 + 0], v1 = ls4[(2 * q + 1) * 4 + 1];
                float4 v2 = ls4[(2 * q + 1) * 4 + 2], v3 = ls4[(2 * q + 1) * 4 + 3];
                oacc[0]  = fmaf(r1, v0.x, oacc[0]);  oacc[1]  = fmaf(r1, v0.y, oacc[1]);
                oacc[2]  = fmaf(r1, v0.z, oacc[2]);  oacc[3]  = fmaf(r1, v0.w, oacc[3]);
                oacc[4]  = fmaf(r1, v1.x, oacc[4]);  oacc[5]  = fmaf(r1, v1.y, oacc[5]);
                oacc[6]  = fmaf(r1, v1.z, oacc[6]);  oacc[7]  = fmaf(r1, v1.w, oacc[7]);
                oacc[8]  = fmaf(r1, v2.x, oacc[8]);  oacc[9]  = fmaf(r1, v2.y, oacc[9]);
                oacc[10] = fmaf(r1, v2.z, oacc[10]); oacc[11] = fmaf(r1, v2.w, oacc[11]);
                oacc[12] = fmaf(r1, v3.x, oacc[12]); oacc[13] = fmaf(r1, v3.y, oacc[13]);
                oacc[14] = fmaf(r1, v3.z, oacc[14]); oacc[15] = fmaf(r1, v3.w, oacc[15]);
            }
        }

        // sum the 4 trees of this quad (lane-quad butterfly)
#pragma unroll
        for (int o = 0; o < ODIM; o++) {
            oacc[o] += __shfl_xor_sync(0xffffffffu, oacc[o], 1);
            oacc[o] += __shfl_xor_sync(0xffffffffu, oacc[o], 2);
        }
        // all 4 lanes hold the row sum; lane t writes float4 quarter t
        float4 v = make_float4(oacc[t * 4 + 0], oacc[t * 4 + 1],
                               oacc[t * 4 + 2], oacc[t * 4 + 3]);
        *(float4*)&g_outp[((size_t)blockIdx.x * BATCH + mrow_base + row) * ODIM + t * 4] = v;
    }
}

// ---------------- final reduce over the 16 partials ----------------
__global__ void reduce_kernel(float* __restrict__ out) {
    int i = blockIdx.x * blockDim.x + threadIdx.x;   // 32768 float4s
    float4 acc = make_float4(0.f, 0.f, 0.f, 0.f);
#pragma unroll
    for (int g = 0; g < 16; g++) {
        float4 v = ((const float4*)g_outp)[(size_t)g * (BATCH * 4) + i];
        acc.x += v.x; acc.y += v.y; acc.z += v.z; acc.w += v.w;
    }
    const float s = 1.0f / NUM_TREE;
    ((float4*)out)[i] = make_float4(acc.x * s, acc.y * s, acc.z * s, acc.w * s);
}

// ---------------- launch ----------------
extern "C" void kernel_launch(void* const* d_in, const int* in_sizes, int n_in,
                              void* d_out, int out_size) {
    const float* x     = (const float*)d_in[0];   // [8192, 512]
    const float* W     = (const float*)d_in[1];   // [1984, 512]
    const float* b     = (const float*)d_in[2];   // [1984]
    const float* leafs = (const float*)d_in[3];   // [64, 32, 16]
    float* out = (float*)d_out;                   // [8192, 16]

    leafs_softmax_kernel<<<(NUM_TREE * NL + 255) / 256, 256>>>(leafs);
    prep_x_kernel<<<(BATCH * IN_DIM / 2) / 256, 256>>>(x);
    prep_w_kernel<<<(2048 * IN_DIM / 2) / 256, 256>>>(W, b);

    cudaFuncSetAttribute(dndf_mma_kernel,
                         cudaFuncAttributeMaxDynamicSharedMemorySize, SMEM_TOTAL);
    dndf_mma_kernel<<<dim3(NGRP, BATCH / BM), THREADS, SMEM_TOTAL>>>();

    reduce_kernel<<<(BATCH * 4) / 256, 256>>>(out);
}

// round 15
// speedup vs baseline: 2.2035x; 1.9361x over previous
#include <cuda_runtime.h>
#include <cuda_bf16.h>
#include <cuda_fp16.h>
#include <cstdint>

// ---------------- problem constants ----------------
#define BATCH    8192
#define IN_DIM   512
#define NUM_TREE 64
#define NI       31
#define NL       32
#define ODIM     16

// ---------------- GEMM1 tiling (bf16 m16n8k16, fragment-major, direct LDG) ----------------
#define BM       128
#define BN       256         // 8 trees * 32 padded cols
#define NK16     (IN_DIM / 16)   // 32 k16 steps
#define THREADS  512         // 16 warps: 2 m-groups x 8 n-groups, 64x32 warp tiles
#define NGRP     8           // N groups (8 * 256 = 2048 padded nodes)

// smem: p buffer + route A-fragments + bias
#define P_PITCH   261
#define UOFF_P    0u                           // float[128*261] = 133632 B
#define UOFF_AF   133632u                      // u32[8*16*32*4] = 65536 B (route frags)
#define UOFF_BIAS 199168u                      // float[256]     = 1024 B
#define SMEM_TOTAL 200192u                     // 1 CTA/SM

// ---------------- device scratch ----------------
// A fragments (bf16x2 words): [512 mtiles][32 k16][32 lanes][4 regs] = 8.4 MB
__device__ __align__(16) uint32_t g_A[(size_t)BATCH * IN_DIM / 2];
// B fragments (bf16x2 words): [256 ntiles][32 k16][32 lanes][2 regs] = 2 MB
__device__ __align__(16) uint32_t g_B[(size_t)2048 * IN_DIM / 2];
// Leaf B fragments (fp16x2): [8 grp][2 nt][16 s][32 lane][2 reg] = 16384 u32
__device__ __align__(16) uint32_t g_LB[16384];
__device__ __align__(16) float g_bp[2048];
__device__ __align__(16) float g_leafs_sm[NUM_TREE * NL * ODIM];
__device__ __align__(16) float g_outp[(size_t)NGRP * BATCH * ODIM];  // 8 partials, 4 MB

// ---------------- helpers ----------------
__device__ __forceinline__ void ldg128(uint32_t* r, const uint32_t* p) {
    asm volatile("ld.global.nc.v4.b32 {%0,%1,%2,%3}, [%4];"
                 : "=r"(r[0]), "=r"(r[1]), "=r"(r[2]), "=r"(r[3]) : "l"(p));
}
__device__ __forceinline__ void ldg64(uint32_t* r, const uint32_t* p) {
    asm volatile("ld.global.nc.v2.b32 {%0,%1}, [%2];" : "=r"(r[0]), "=r"(r[1]) : "l"(p));
}
__device__ __forceinline__ void mma_bf16(float& c0, float& c1, float& c2, float& c3,
                                         uint32_t a0, uint32_t a1, uint32_t a2, uint32_t a3,
                                         uint32_t b0, uint32_t b1) {
    asm volatile("mma.sync.aligned.m16n8k16.row.col.f32.bf16.bf16.f32 "
                 "{%0,%1,%2,%3}, {%4,%5,%6,%7}, {%8,%9}, {%0,%1,%2,%3};"
                 : "+f"(c0), "+f"(c1), "+f"(c2), "+f"(c3)
                 : "r"(a0), "r"(a1), "r"(a2), "r"(a3), "r"(b0), "r"(b1));
}
__device__ __forceinline__ void mma_fp16(float& c0, float& c1, float& c2, float& c3,
                                         uint32_t a0, uint32_t a1, uint32_t a2, uint32_t a3,
                                         uint32_t b0, uint32_t b1) {
    asm volatile("mma.sync.aligned.m16n8k16.row.col.f32.f16.f16.f32 "
                 "{%0,%1,%2,%3}, {%4,%5,%6,%7}, {%8,%9}, {%0,%1,%2,%3};"
                 : "+f"(c0), "+f"(c1), "+f"(c2), "+f"(c3)
                 : "r"(a0), "r"(a1), "r"(a2), "r"(a3), "r"(b0), "r"(b1));
}
__device__ __forceinline__ uint32_t pack_bf16x2(float lo, float hi) {
    __nv_bfloat162 h;
    h.x = __float2bfloat16(lo);
    h.y = __float2bfloat16(hi);
    return *(const uint32_t*)&h;
}

// ---------------- prep kernels ----------------
__global__ void leafs_softmax_kernel(const float* __restrict__ leafs) {
    int i = blockIdx.x * blockDim.x + threadIdx.x;
    if (i >= NUM_TREE * NL) return;
    const float* src = leafs + i * ODIM;
    float m = src[0];
#pragma unroll
    for (int o = 1; o < ODIM; o++) m = fmaxf(m, src[o]);
    float e[ODIM], sum = 0.f;
#pragma unroll
    for (int o = 0; o < ODIM; o++) { e[o] = __expf(src[o] - m); sum += e[o]; }
    float inv = 1.0f / sum;
#pragma unroll
    for (int o = 0; o < ODIM; o++) g_leafs_sm[i * ODIM + o] = e[o] * inv;
}

// leafs_sm -> fp16 B fragments for GEMM2 (m16n8k16, col-major B):
// linear i = (((grp*2+nt)*16+s)*32+lane)*2+reg
__global__ void prep_leaf_kernel() {
    int i = blockIdx.x * blockDim.x + threadIdx.x;   // 0..16383
    int reg  = i & 1;
    int lane = (i >> 1) & 31;
    int s    = (i >> 6) & 15;
    int nt   = (i >> 10) & 1;
    int grp  = i >> 11;
    int n  = nt * 8 + (lane >> 2);
    int k0 = s * 16 + (lane & 3) * 2 + reg * 8;      // even
    int tree = grp * 8 + (k0 >> 5);
    int leaf = k0 & 31;
    float v0 = g_leafs_sm[(tree * 32 + leaf) * ODIM + n];
    float v1 = g_leafs_sm[(tree * 32 + leaf + 1) * ODIM + n];
    __half2 h = __floats2half2_rn(v0, v1);
    g_LB[i] = *(const uint32_t*)&h;
}

// x -> bf16x2 A fragments, m16n8k16 layout: [mtile][k16][lane][reg]
__global__ void prep_x_kernel(const float* __restrict__ x) {
    int i = blockIdx.x * blockDim.x + threadIdx.x;   // 0 .. BATCH*IN_DIM/2-1
    int mtile = i >> 12;
    int rem   = i & 4095;
    int step  = rem >> 7;
    int rem2  = rem & 127;
    int lane  = rem2 >> 2;
    int reg   = rem2 & 3;
    int g = lane >> 2, t = lane & 3;
    int row = mtile * 16 + g + (reg & 1) * 8;
    int k0  = step * 16 + 2 * t + ((reg >> 1) & 1) * 8;
    const float* xp = x + (size_t)row * IN_DIM + k0;
    g_A[i] = pack_bf16x2(xp[0], xp[1]);
}

// W (tree-permuted, node31 zero) -> bf16x2 B fragments: [ntile][k16][lane][reg]
__global__ void prep_w_kernel(const float* __restrict__ W, const float* __restrict__ b) {
    int i = blockIdx.x * blockDim.x + threadIdx.x;   // 0 .. 2048*IN_DIM/2-1
    int ntile = i >> 11;
    int rem   = i & 2047;
    int step  = rem >> 6;
    int rem2  = rem & 63;
    int lane  = rem2 >> 1;
    int reg   = rem2 & 1;
    int g = lane >> 2, t = lane & 3;
    int n = ntile * 8 + g;
    int tree = n >> 5, ii = n & 31;
    int k0 = step * 16 + 2 * t + reg * 8;
    float v0 = 0.f, v1 = 0.f;
    if (ii < 31) {
        const float* wp = W + (size_t)(tree * 31 + ii) * IN_DIM + k0;
        v0 = wp[0]; v1 = wp[1];
    }
    g_B[i] = pack_bf16x2(v0, v1);
    if (step == 0 && t == 0 && reg == 0)
        g_bp[n] = (ii < 31) ? b[tree * 31 + ii] : 0.f;
}

// ---------------- fused GEMM1 + routing + GEMM2 kernel ----------------
__global__ __launch_bounds__(THREADS, 1)
void dndf_mma_kernel() {
    extern __shared__ char smem[];

    const int tid = threadIdx.x;
    const int wid = tid >> 5;
    const int lid = tid & 31;
    const int wm = wid & 1;          // 2 m-groups of 64 rows (4 mtiles)
    const int wn = wid >> 1;         // 8 n-groups of 32 cols (4 ntiles)
    const int bm8  = blockIdx.y * 8;    // first mtile of CTA
    const int bn32 = blockIdx.x * 32;   // first ntile of CTA
    const int mrow_base = blockIdx.y * BM;
    const int ncol_base = blockIdx.x * BN;

    float*    p_s    = (float*)(smem + UOFF_P);
    uint32_t* af     = (uint32_t*)(smem + UOFF_AF);
    float*    bias_s = (float*)(smem + UOFF_BIAS);

    // ---- stage bias BEFORE mainloop (sync after mainloop covers it) ----
    if (tid < 256) bias_s[tid] = g_bp[ncol_base + tid];

    // ---- fragment pointers (GEMM1) ----
    const uint32_t* a_ptr = g_A + ((size_t)(bm8 + wm * 4) * 4096) + lid * 4;
    const uint32_t* b_ptr = g_B + ((size_t)(bn32 + wn * 4) * 2048) + lid * 2;

    float acc[4][4][4];
#pragma unroll
    for (int i = 0; i < 4; i++)
#pragma unroll
        for (int j = 0; j < 4; j++)
#pragma unroll
            for (int r = 0; r < 4; r++) acc[i][j][r] = 0.f;

    uint32_t a[2][4][4], b[2][4][2];
#pragma unroll
    for (int mi = 0; mi < 4; mi++) ldg128(a[0][mi], a_ptr + mi * 4096);
#pragma unroll
    for (int nb = 0; nb < 4; nb++) ldg64(b[0][nb], b_ptr + nb * 2048);

#pragma unroll 1
    for (int k = 0; k < NK16; k += 2) {
        {
            const uint32_t* ap = a_ptr + (size_t)(k + 1) * 128;
            const uint32_t* bp = b_ptr + (size_t)(k + 1) * 64;
#pragma unroll
            for (int mi = 0; mi < 4; mi++) ldg128(a[1][mi], ap + mi * 4096);
#pragma unroll
            for (int nb = 0; nb < 4; nb++) ldg64(b[1][nb], bp + nb * 2048);
#pragma unroll
            for (int mi = 0; mi < 4; mi++)
#pragma unroll
                for (int nb = 0; nb < 4; nb++)
                    mma_bf16(acc[mi][nb][0], acc[mi][nb][1], acc[mi][nb][2], acc[mi][nb][3],
                             a[0][mi][0], a[0][mi][1], a[0][mi][2], a[0][mi][3],
                             b[0][nb][0], b[0][nb][1]);
        }
        {
            if (k + 2 < NK16) {
                const uint32_t* ap = a_ptr + (size_t)(k + 2) * 128;
                const uint32_t* bp = b_ptr + (size_t)(k + 2) * 64;
#pragma unroll
                for (int mi = 0; mi < 4; mi++) ldg128(a[0][mi], ap + mi * 4096);
#pragma unroll
                for (int nb = 0; nb < 4; nb++) ldg64(b[0][nb], bp + nb * 2048);
            }
#pragma unroll
            for (int mi = 0; mi < 4; mi++)
#pragma unroll
                for (int nb = 0; nb < 4; nb++)
                    mma_bf16(acc[mi][nb][0], acc[mi][nb][1], acc[mi][nb][2], acc[mi][nb][3],
                             a[1][mi][0], a[1][mi][1], a[1][mi][2], a[1][mi][3],
                             b[1][nb][0], b[1][nb][1]);
        }
    }

    __syncthreads();   // bias staged; p_s free to fill

    // ---- sigmoid(acc + bias) -> p_s, tree-interleaved: p_s[row][node*8 + tree] ----
#pragma unroll
    for (int mi = 0; mi < 4; mi++) {
#pragma unroll
        for (int nb = 0; nb < 4; nb++) {
            const int colb = wn * 32 + nb * 8 + (lid & 3) * 2;
            const int rowb = wm * 64 + mi * 16 + (lid >> 2);
#pragma unroll
            for (int r = 0; r < 4; r++) {
                const int row = rowb + (r >> 1) * 8;
                const int col = colb + (r & 1);           // 0..255 = tree*32 + node
                const int icol = (col & 31) * 8 + (col >> 5);
                const float v = acc[mi][nb][r] + bias_s[col];
                p_s[row * P_PITCH + icol] = 1.0f / (1.0f + __expf(-v));
            }
        }
    }
    __syncthreads();

    // ---- routing: compute route probs, store as fp16 A-fragments into af ----
    // 1024 tasks (row, tree), 2 per thread. af layout: [mt(8)][s(16)][lane(32)][reg(4)] u32
    {
        const int tq = lid & 3;
        const int rowq = lid >> 2;
#pragma unroll 1
        for (int j = 0; j < 2; j++) {
            const int t = tq + 4 * j;              // tree within CTA group (0..7)
            const int row = wid * 8 + rowq;
            const float* P = &p_s[row * P_PITCH + t];   // node i at P[i*8]

            float bb[4], cc[8], dd[16];
            {
                float p0 = P[0];
                float p1 = P[8], p2 = P[16];
                float s01 = p0 * p1;
                float s02 = p2 - p0 * p2;
                bb[0] = s01;         bb[1] = p0 - s01;
                bb[2] = s02;         bb[3] = (1.0f - p0) - s02;
            }
#pragma unroll
            for (int q = 0; q < 4; q++) {
                float pv = P[(3 + q) * 8];
                float s = bb[q] * pv;
                cc[2 * q] = s; cc[2 * q + 1] = bb[q] - s;
            }
#pragma unroll
            for (int q = 0; q < 8; q++) {
                float pv = P[(7 + q) * 8];
                float s = cc[q] * pv;
                dd[2 * q] = s; dd[2 * q + 1] = cc[q] - s;
            }

            const int mt = row >> 4, g = row & 7, hi = (row >> 3) & 1;
#pragma unroll
            for (int q = 0; q < 16; q++) {
                float pv = P[(15 + q) * 8];
                float r0 = dd[q] * pv;
                float r1 = dd[q] - r0;
                __half2 h = __floats2half2_rn(r0, r1);
                const int s  = 2 * t + (q >> 3);
                const int idx = ((mt * 16 + s) * 32 + g * 4 + (q & 3)) * 4
                                + ((q >> 2) & 1) * 2 + hi;
                af[idx] = *(const uint32_t*)&h;
            }
        }
    }
    __syncthreads();

    // ---- GEMM2: out_partial[128x16] = routes[128x256] @ leafs_fp16[256x16] ----
    // 16 warps = 8 mtiles x 2 ntiles; per warp: 16 k16 steps.
    {
        const int mt = wid >> 1;
        const int nt = wid & 1;
        uint32_t bf[16][2];
        const uint32_t* lb = g_LB + (((size_t)(blockIdx.x * 2 + nt) * 16) * 32 + lid) * 2;
#pragma unroll
        for (int s = 0; s < 16; s++) ldg64(bf[s], lb + s * 64);

        float c0 = 0.f, c1 = 0.f, c2 = 0.f, c3 = 0.f;
#pragma unroll
        for (int s = 0; s < 16; s++) {
            uint4 a4 = *(const uint4*)&af[((mt * 16 + s) * 32 + lid) * 4];
            mma_fp16(c0, c1, c2, c3, a4.x, a4.y, a4.z, a4.w, bf[s][0], bf[s][1]);
        }

        const int row0 = mrow_base + mt * 16 + (lid >> 2);
        const int n0 = nt * 8 + (lid & 3) * 2;
        float* op = &g_outp[((size_t)blockIdx.x * BATCH + row0) * ODIM + n0];
        *(float2*)op = make_float2(c0, c1);
        *(float2*)(op + 8 * ODIM) = make_float2(c2, c3);
    }
}

// ---------------- final reduce over the 8 partials ----------------
__global__ void reduce_kernel(float* __restrict__ out) {
    int i = blockIdx.x * blockDim.x + threadIdx.x;   // 32768 float4s
    float4 acc = make_float4(0.f, 0.f, 0.f, 0.f);
#pragma unroll
    for (int g = 0; g < NGRP; g++) {
        float4 v = ((const float4*)g_outp)[(size_t)g * (BATCH * 4) + i];
        acc.x += v.x; acc.y += v.y; acc.z += v.z; acc.w += v.w;
    }
    const float s = 1.0f / NUM_TREE;
    ((float4*)out)[i] = make_float4(acc.x * s, acc.y * s, acc.z * s, acc.w * s);
}

// ---------------- launch ----------------
extern "C" void kernel_launch(void* const* d_in, const int* in_sizes, int n_in,
                              void* d_out, int out_size) {
    const float* x     = (const float*)d_in[0];   // [8192, 512]
    const float* W     = (const float*)d_in[1];   // [1984, 512]
    const float* b     = (const float*)d_in[2];   // [1984]
    const float* leafs = (const float*)d_in[3];   // [64, 32, 16]
    float* out = (float*)d_out;                   // [8192, 16]

    leafs_softmax_kernel<<<(NUM_TREE * NL + 255) / 256, 256>>>(leafs);
    prep_leaf_kernel<<<16384 / 256, 256>>>();
    prep_x_kernel<<<(BATCH * IN_DIM / 2) / 256, 256>>>(x);
    prep_w_kernel<<<(2048 * IN_DIM / 2) / 256, 256>>>(W, b);

    cudaFuncSetAttribute(dndf_mma_kernel,
                         cudaFuncAttributeMaxDynamicSharedMemorySize, SMEM_TOTAL);
    dndf_mma_kernel<<<dim3(NGRP, BATCH / BM), THREADS, SMEM_TOTAL>>>();

    reduce_kernel<<<(BATCH * 4) / 256, 256>>>(out);
}